// round 6
// baseline (speedup 1.0000x reference)
#include <cuda_runtime.h>
#include <cstdint>

#define TT  50
#define FF  24
#define H1  64
#define LAT 32
#define H3  64
#define BMAX 8192

typedef unsigned long long u64;

__device__ float g_h1[(size_t)BMAX * TT * H1];   // [B][T][64]
__device__ float g_z [(size_t)BMAX * LAT];

__device__ __forceinline__ float sigmoidf(float v) {
    return __fdividef(1.0f, 1.0f + __expf(-v));
}
__device__ __forceinline__ u64 ffma2(u64 a, u64 b, u64 c) {
    u64 d; asm("fma.rn.f32x2 %0, %1, %2, %3;" : "=l"(d) : "l"(a), "l"(b), "l"(c)); return d;
}
__device__ __forceinline__ u64 pack2(float lo, float hi) {
    u64 r; asm("mov.b64 %0, {%1, %2};" : "=l"(r) : "f"(lo), "f"(hi)); return r;
}
__device__ __forceinline__ float2 unpack2(u64 v) {
    float2 f; asm("mov.b64 {%0, %1}, %2;" : "=f"(f.x), "=f"(f.y) : "l"(v)); return f;
}

// ---------------------------------------------------------------------------
// LSTM1: x[B,T,24] -> g_h1[B,T,64]
// 256 threads = 128 column-pairs x 2 k-halves. R=8 rows/block.
// k-halves over combined [x(24); h(64)]: kh0 = x + h[0:20], kh1 = h[20:64].
// Partials land in zp[kh]; gate epilogue sums both halves.
// ---------------------------------------------------------------------------
__global__ void __launch_bounds__(256, 2) lstm1_kernel(
    const float* __restrict__ x, const float* __restrict__ W,
    const float* __restrict__ U, const float* __restrict__ b, int B)
{
    constexpr int D = FF, H = H1, G = 4 * H1, R = 8;
    __shared__ __align__(16) float xs[2][R][D];
    __shared__ __align__(16) float hs[R][H];
    __shared__ __align__(16) float zp[2][R][G];

    const int j    = threadIdx.x;
    const int c2   = j & 127;
    const int kh   = j >> 7;
    const int cA   = 2 * c2, cB = cA + 1;
    const int row0 = blockIdx.x * R;

    u64 wA[22], wB[22];
    if (kh == 0) {
#pragma unroll
        for (int kp = 0; kp < 12; kp++) {
            wA[kp] = pack2(W[(2 * kp) * G + cA], W[(2 * kp + 1) * G + cA]);
            wB[kp] = pack2(W[(2 * kp) * G + cB], W[(2 * kp + 1) * G + cB]);
        }
#pragma unroll
        for (int kp = 0; kp < 10; kp++) {
            wA[12 + kp] = pack2(U[(2 * kp) * G + cA], U[(2 * kp + 1) * G + cA]);
            wB[12 + kp] = pack2(U[(2 * kp) * G + cB], U[(2 * kp + 1) * G + cB]);
        }
    } else {
#pragma unroll
        for (int kp = 0; kp < 22; kp++) {
            const int h0 = 20 + 2 * kp;
            wA[kp] = pack2(U[h0 * G + cA], U[(h0 + 1) * G + cA]);
            wB[kp] = pack2(U[h0 * G + cB], U[(h0 + 1) * G + cB]);
        }
    }
    const u64 iA = (kh == 0) ? pack2(b[cA], 0.0f) : 0ull;
    const u64 iB = (kh == 0) ? pack2(b[cB], 0.0f) : 0ull;

    for (int idx = j; idx < R * H; idx += 256) (&hs[0][0])[idx] = 0.0f;

    const int um = j & 63, rb = j >> 6;   // 512 gate tasks over 256 threads
    float cst[2] = {0.0f, 0.0f};

    // x staging: 192 elems, one per thread j<192
    const int lr = j / D, lk = j - lr * D;
    float xreg = 0.0f;
    if (j < R * D) {
        int rc = min(row0 + lr, B - 1);
        xreg = x[((size_t)rc * TT + 0) * D + lk];
    }

    int buf = 0;
    for (int t = 0; t < TT; t++) {
        if (j < R * D) {
            xs[buf][lr][lk] = xreg;
            if (t + 1 < TT) {
                int rc = min(row0 + lr, B - 1);
                xreg = x[((size_t)rc * TT + (t + 1)) * D + lk];
            }
        }
        __syncthreads();   // A: xs + hs(t-1) visible; prior gate reads of zp done

        u64 aA[R], aB[R];
#pragma unroll
        for (int r = 0; r < R; r++) { aA[r] = iA; aB[r] = iB; }
        if (kh == 0) {
#pragma unroll
            for (int g = 0; g < 6; g++) {
#pragma unroll
                for (int r = 0; r < R; r++) {
                    const ulonglong2 xv = *(const ulonglong2*)&xs[buf][r][4 * g];
                    aA[r] = ffma2(xv.x, wA[2 * g], aA[r]);
                    aA[r] = ffma2(xv.y, wA[2 * g + 1], aA[r]);
                    aB[r] = ffma2(xv.x, wB[2 * g], aB[r]);
                    aB[r] = ffma2(xv.y, wB[2 * g + 1], aB[r]);
                }
            }
#pragma unroll
            for (int g = 0; g < 5; g++) {
#pragma unroll
                for (int r = 0; r < R; r++) {
                    const ulonglong2 hv = *(const ulonglong2*)&hs[r][4 * g];
                    aA[r] = ffma2(hv.x, wA[12 + 2 * g], aA[r]);
                    aA[r] = ffma2(hv.y, wA[13 + 2 * g], aA[r]);
                    aB[r] = ffma2(hv.x, wB[12 + 2 * g], aB[r]);
                    aB[r] = ffma2(hv.y, wB[13 + 2 * g], aB[r]);
                }
            }
        } else {
#pragma unroll
            for (int g = 0; g < 11; g++) {
#pragma unroll
                for (int r = 0; r < R; r++) {
                    const ulonglong2 hv = *(const ulonglong2*)&hs[r][20 + 4 * g];
                    aA[r] = ffma2(hv.x, wA[2 * g], aA[r]);
                    aA[r] = ffma2(hv.y, wA[2 * g + 1], aA[r]);
                    aB[r] = ffma2(hv.x, wB[2 * g], aB[r]);
                    aB[r] = ffma2(hv.y, wB[2 * g + 1], aB[r]);
                }
            }
        }
#pragma unroll
        for (int r = 0; r < R; r++) {
            const float2 pA = unpack2(aA[r]);
            const float2 pB = unpack2(aB[r]);
            *(float2*)&zp[kh][r][cA] = make_float2(pA.x + pA.y, pB.x + pB.y);
        }
        __syncthreads();   // B: both partial halves ready; hs reads done

#pragma unroll
        for (int q = 0; q < 2; q++) {
            const int r = rb + 4 * q;
            float zi = zp[0][r][um]       + zp[1][r][um];
            float zf = zp[0][r][64 + um]  + zp[1][r][64 + um];
            float zg = zp[0][r][128 + um] + zp[1][r][128 + um];
            float zo = zp[0][r][192 + um] + zp[1][r][192 + um];
            cst[q] = sigmoidf(zf) * cst[q] + sigmoidf(zi) * fmaxf(zg, 0.0f);
            float hn = sigmoidf(zo) * fmaxf(cst[q], 0.0f);
            hs[r][um] = hn;
            if (row0 + r < B) g_h1[((size_t)(row0 + r) * TT + t) * H + um] = hn;
        }
        buf ^= 1;
    }
}

// ---------------------------------------------------------------------------
// LSTM2: g_h1[B,T,64] -> g_z[B,32]
// 128 threads = 64 column-pairs x 2 k-halves. kh0 = x[0:48], kh1 = x[48:64]+h.
// ---------------------------------------------------------------------------
__global__ void __launch_bounds__(128, 3) lstm2_kernel(
    const float* __restrict__ W, const float* __restrict__ U,
    const float* __restrict__ b, int B)
{
    constexpr int D = H1, H = LAT, G = 4 * LAT, R = 8;
    __shared__ __align__(16) float xs[2][R][D];
    __shared__ __align__(16) float hs[R][H];
    __shared__ __align__(16) float zp[2][R][G];

    const int j    = threadIdx.x;
    const int c2   = j & 63;
    const int kh   = j >> 6;
    const int cA   = 2 * c2, cB = cA + 1;
    const int row0 = blockIdx.x * R;

    u64 wA[24], wB[24];
    if (kh == 0) {
#pragma unroll
        for (int kp = 0; kp < 24; kp++) {
            wA[kp] = pack2(W[(2 * kp) * G + cA], W[(2 * kp + 1) * G + cA]);
            wB[kp] = pack2(W[(2 * kp) * G + cB], W[(2 * kp + 1) * G + cB]);
        }
    } else {
#pragma unroll
        for (int kp = 0; kp < 8; kp++) {
            const int x0 = 48 + 2 * kp;
            wA[kp] = pack2(W[x0 * G + cA], W[(x0 + 1) * G + cA]);
            wB[kp] = pack2(W[x0 * G + cB], W[(x0 + 1) * G + cB]);
        }
#pragma unroll
        for (int kp = 0; kp < 16; kp++) {
            wA[8 + kp] = pack2(U[(2 * kp) * G + cA], U[(2 * kp + 1) * G + cA]);
            wB[8 + kp] = pack2(U[(2 * kp) * G + cB], U[(2 * kp + 1) * G + cB]);
        }
    }
    const u64 iA = (kh == 0) ? pack2(b[cA], 0.0f) : 0ull;
    const u64 iB = (kh == 0) ? pack2(b[cB], 0.0f) : 0ull;

    for (int idx = j; idx < R * H; idx += 128) (&hs[0][0])[idx] = 0.0f;

    const int um = j & 31, rb = j >> 5;   // 0..3
    float cst[2] = {0.0f, 0.0f};

    // staging: 512 floats / 128 threads = 1 float4 each
    const int lr = j >> 4, lk = (j & 15) * 4;
    float4 xreg;
    {
        int row = min(row0 + lr, B - 1);
        xreg = *(const float4*)&g_h1[((size_t)row * TT + 0) * D + lk];
    }

    int buf = 0;
    for (int t = 0; t < TT; t++) {
        *(float4*)&xs[buf][lr][lk] = xreg;
        if (t + 1 < TT) {
            int row = min(row0 + lr, B - 1);
            xreg = *(const float4*)&g_h1[((size_t)row * TT + (t + 1)) * D + lk];
        }
        __syncthreads();

        u64 aA[R], aB[R];
#pragma unroll
        for (int r = 0; r < R; r++) { aA[r] = iA; aB[r] = iB; }
        if (kh == 0) {
#pragma unroll
            for (int g = 0; g < 12; g++) {
#pragma unroll
                for (int r = 0; r < R; r++) {
                    const ulonglong2 xv = *(const ulonglong2*)&xs[buf][r][4 * g];
                    aA[r] = ffma2(xv.x, wA[2 * g], aA[r]);
                    aA[r] = ffma2(xv.y, wA[2 * g + 1], aA[r]);
                    aB[r] = ffma2(xv.x, wB[2 * g], aB[r]);
                    aB[r] = ffma2(xv.y, wB[2 * g + 1], aB[r]);
                }
            }
        } else {
#pragma unroll
            for (int g = 0; g < 4; g++) {
#pragma unroll
                for (int r = 0; r < R; r++) {
                    const ulonglong2 xv = *(const ulonglong2*)&xs[buf][r][48 + 4 * g];
                    aA[r] = ffma2(xv.x, wA[2 * g], aA[r]);
                    aA[r] = ffma2(xv.y, wA[2 * g + 1], aA[r]);
                    aB[r] = ffma2(xv.x, wB[2 * g], aB[r]);
                    aB[r] = ffma2(xv.y, wB[2 * g + 1], aB[r]);
                }
            }
#pragma unroll
            for (int g = 0; g < 8; g++) {
#pragma unroll
                for (int r = 0; r < R; r++) {
                    const ulonglong2 hv = *(const ulonglong2*)&hs[r][4 * g];
                    aA[r] = ffma2(hv.x, wA[8 + 2 * g], aA[r]);
                    aA[r] = ffma2(hv.y, wA[9 + 2 * g], aA[r]);
                    aB[r] = ffma2(hv.x, wB[8 + 2 * g], aB[r]);
                    aB[r] = ffma2(hv.y, wB[9 + 2 * g], aB[r]);
                }
            }
        }
#pragma unroll
        for (int r = 0; r < R; r++) {
            const float2 pA = unpack2(aA[r]);
            const float2 pB = unpack2(aB[r]);
            *(float2*)&zp[kh][r][cA] = make_float2(pA.x + pA.y, pB.x + pB.y);
        }
        __syncthreads();

#pragma unroll
        for (int q = 0; q < 2; q++) {
            const int r = rb + 4 * q;
            float zi = zp[0][r][um]      + zp[1][r][um];
            float zf = zp[0][r][32 + um] + zp[1][r][32 + um];
            float zg = zp[0][r][64 + um] + zp[1][r][64 + um];
            float zo = zp[0][r][96 + um] + zp[1][r][96 + um];
            cst[q] = sigmoidf(zf) * cst[q] + sigmoidf(zi) * fmaxf(zg, 0.0f);
            float hn = sigmoidf(zo) * fmaxf(cst[q], 0.0f);
            hs[r][um] = hn;
            if (t == TT - 1 && row0 + r < B) g_z[(size_t)(row0 + r) * H + um] = hn;
        }
        buf ^= 1;
    }
}

// ---------------------------------------------------------------------------
// LSTM3 + Dense: g_z[B,32] -> out[B,T,24]
// 256 threads = 128 column-pairs x 2 k-halves over h (x-proj hoisted).
// ---------------------------------------------------------------------------
__global__ void __launch_bounds__(256, 2) lstm3_kernel(
    const float* __restrict__ W, const float* __restrict__ U,
    const float* __restrict__ b, const float* __restrict__ Wd,
    const float* __restrict__ bd, float* __restrict__ out, int B)
{
    constexpr int D = LAT, H = H3, G = 4 * H3, R = 8;
    constexpr int WDP = 68;
    __shared__ __align__(16) float zin[R][D];
    __shared__ __align__(16) float hs[R][H];
    __shared__ __align__(16) float zp[2][R][G];
    __shared__ __align__(16) float wdst[FF][WDP];

    const int j    = threadIdx.x;
    const int c2   = j & 127;
    const int kh   = j >> 7;
    const int cA   = 2 * c2, cB = cA + 1;
    const int row0 = blockIdx.x * R;
    const int hb   = 32 * kh;

    u64 uA[16], uB[16];
#pragma unroll
    for (int kp = 0; kp < 16; kp++) {
        const int h0 = hb + 2 * kp;
        uA[kp] = pack2(U[h0 * G + cA], U[(h0 + 1) * G + cA]);
        uB[kp] = pack2(U[h0 * G + cB], U[(h0 + 1) * G + cB]);
    }

    for (int idx = j; idx < H * FF; idx += 256) {
        int h = idx / FF, f = idx - h * FF;
        wdst[f][h] = Wd[idx];
    }
    {
        int r = j >> 5, k = j & 31;
        if (j < R * D) {
            int row = min(row0 + r, B - 1);
            zin[r][k] = g_z[(size_t)row * D + k];
        }
    }
    for (int idx = j; idx < R * H; idx += 256) (&hs[0][0])[idx] = 0.0f;
    __syncthreads();

    // per-half x-projection (constant over t): kh0 takes k 0..15 + bias, kh1 k 16..31
    float zwA[R], zwB[R];
    {
        const int kb = 16 * kh;
        const float bvA = (kh == 0) ? b[cA] : 0.0f;
        const float bvB = (kh == 0) ? b[cB] : 0.0f;
#pragma unroll
        for (int r = 0; r < R; r++) { zwA[r] = bvA; zwB[r] = bvB; }
#pragma unroll
        for (int k = 0; k < 16; k++) {
            const float wkA = W[(kb + k) * G + cA], wkB = W[(kb + k) * G + cB];
#pragma unroll
            for (int r = 0; r < R; r++) {
                zwA[r] += zin[r][kb + k] * wkA;
                zwB[r] += zin[r][kb + k] * wkB;
            }
        }
    }

    const int um = j & 63, rb = j >> 6;
    float cst[2] = {0.0f, 0.0f};

    const int df = j % FF, dr = j / FF;   // dense task (j < 192)
    const float bdf = (j < R * FF) ? bd[df] : 0.0f;

    for (int t = 0; t < TT; t++) {
        u64 aA[R], aB[R];
#pragma unroll
        for (int r = 0; r < R; r++) {
            aA[r] = pack2(zwA[r], 0.0f);
            aB[r] = pack2(zwB[r], 0.0f);
        }
#pragma unroll
        for (int g = 0; g < 8; g++) {
#pragma unroll
            for (int r = 0; r < R; r++) {
                const ulonglong2 hv = *(const ulonglong2*)&hs[r][hb + 4 * g];
                aA[r] = ffma2(hv.x, uA[2 * g], aA[r]);
                aA[r] = ffma2(hv.y, uA[2 * g + 1], aA[r]);
                aB[r] = ffma2(hv.x, uB[2 * g], aB[r]);
                aB[r] = ffma2(hv.y, uB[2 * g + 1], aB[r]);
            }
        }
#pragma unroll
        for (int r = 0; r < R; r++) {
            const float2 pA = unpack2(aA[r]);
            const float2 pB = unpack2(aB[r]);
            *(float2*)&zp[kh][r][cA] = make_float2(pA.x + pA.y, pB.x + pB.y);
        }
        __syncthreads();   // S2: partials ready, hs reads (MMA+dense) done

#pragma unroll
        for (int q = 0; q < 2; q++) {
            const int r = rb + 4 * q;
            float zi = zp[0][r][um]       + zp[1][r][um];
            float zf = zp[0][r][64 + um]  + zp[1][r][64 + um];
            float zg = zp[0][r][128 + um] + zp[1][r][128 + um];
            float zo = zp[0][r][192 + um] + zp[1][r][192 + um];
            cst[q] = sigmoidf(zf) * cst[q] + sigmoidf(zi) * fmaxf(zg, 0.0f);
            float hn = sigmoidf(zo) * fmaxf(cst[q], 0.0f);
            hs[r][um] = hn;
        }
        __syncthreads();   // S3: hs(t) visible

        if (j < R * FF) {
            int row = row0 + dr;
            if (row < B) {
                u64 sacc = pack2(bdf, 0.0f);
#pragma unroll
                for (int k = 0; k < H / 4; k++) {
                    const ulonglong2 hv = *(const ulonglong2*)&hs[dr][4 * k];
                    const ulonglong2 wv = *(const ulonglong2*)&wdst[df][4 * k];
                    sacc = ffma2(hv.x, wv.x, sacc);
                    sacc = ffma2(hv.y, wv.y, sacc);
                }
                const float2 p = unpack2(sacc);
                out[((size_t)row * TT + t) * FF + df] = p.x + p.y;
            }
        }
    }
}

// ---------------------------------------------------------------------------
extern "C" void kernel_launch(void* const* d_in, const int* in_sizes, int n_in,
                              void* d_out, int out_size)
{
    const float* x  = (const float*)d_in[0];
    const float* W1 = (const float*)d_in[1];
    const float* U1 = (const float*)d_in[2];
    const float* b1 = (const float*)d_in[3];
    const float* W2 = (const float*)d_in[4];
    const float* U2 = (const float*)d_in[5];
    const float* b2 = (const float*)d_in[6];
    const float* W3 = (const float*)d_in[7];
    const float* U3 = (const float*)d_in[8];
    const float* b3 = (const float*)d_in[9];
    const float* Wd = (const float*)d_in[10];
    const float* bd = (const float*)d_in[11];
    float* out = (float*)d_out;

    const int B = in_sizes[0] / (TT * FF);
    const int nblk = (B + 7) / 8;

    lstm1_kernel<<<nblk, 256>>>(x, W1, U1, b1, B);
    lstm2_kernel<<<nblk, 128>>>(W2, U2, b2, B);
    lstm3_kernel<<<nblk, 256>>>(W3, U3, b3, Wd, bd, out, B);
}